// round 13
// baseline (speedup 1.0000x reference)
#include <cuda_runtime.h>
#include <cuda_bf16.h>
#include <math.h>
#include <stdint.h>

// Problem constants
#define Bq    4
#define CH_G  64
#define Hh    240
#define Ww    320
#define HW    (Hh*Ww)          // 76800
#define NUM   8
#define C_FEA 8
#define COUT  24
#define HIN   120
#define WIN   160
#define Pn    (HW*NUM)         // 614400

// Scratch (device globals; no runtime allocation allowed)
__device__ __align__(16) float g_oaT[(size_t)Bq*HW*COUT];          // conv output, pixel-major (29.5 MB)
__device__ __align__(16) float g_feaT[(size_t)Bq*HW*C_FEA];        // upsampled fea, channel-last (9.8 MB)
__device__ __align__(16) float g_smp[(size_t)Bq*C_FEA*Pn];         // sampled tensor (78.6 MB)
__device__ __align__(16) __nv_bfloat16 g_hi[(size_t)Bq*HW*CH_G];   // guidance NHWC bf16 hi (39.3 MB)
__device__ __align__(16) __nv_bfloat16 g_lo[(size_t)Bq*HW*CH_G];   // guidance NHWC bf16 lo (39.3 MB)

// Padded GEMM rows: 576 k-elements padded to 584 bf16 -> 1168 B/row.
// ldmatrix phases then map 8 consecutive rows onto disjoint bank groups.
#define AROW     1168
#define A_BYTES  (128*AROW)                 // 149504
#define B_HALF   (24*AROW)                  // 28032
#define SMEM_B   A_BYTES
#define SMEM_TOTAL (A_BYTES + 2*B_HALF)     // 205568

__device__ __align__(16) unsigned char g_Bimg[2*B_HALF];   // padded bf16 weight image hi||lo

// ---------------------------------------------------------------------------
// helpers
// ---------------------------------------------------------------------------
__device__ __forceinline__ uint32_t smem_u32(const void* p) {
    uint32_t a;
    asm("{ .reg .u64 t; cvta.to.shared.u64 t, %1; cvt.u32.u64 %0, t; }" : "=r"(a) : "l"(p));
    return a;
}

#define LDSM_X4(r, addr) \
    asm volatile("ldmatrix.sync.aligned.m8n8.x4.shared.b16 {%0,%1,%2,%3}, [%4];" \
        : "=r"((r)[0]), "=r"((r)[1]), "=r"((r)[2]), "=r"((r)[3]) : "r"(addr))

#define LDSM_X2(r, addr) \
    asm volatile("ldmatrix.sync.aligned.m8n8.x2.shared.b16 {%0,%1}, [%2];" \
        : "=r"((r)[0]), "=r"((r)[1]) : "r"(addr))

#define MMA_BF16(c, a, b) \
    asm volatile("mma.sync.aligned.m16n8k16.row.col.f32.bf16.bf16.f32 " \
        "{%0,%1,%2,%3}, {%4,%5,%6,%7}, {%8,%9}, {%0,%1,%2,%3};" \
        : "+f"((c)[0]), "+f"((c)[1]), "+f"((c)[2]), "+f"((c)[3]) \
        : "r"((a)[0]), "r"((a)[1]), "r"((a)[2]), "r"((a)[3]), "r"((b)[0]), "r"((b)[1]))

// ---------------------------------------------------------------------------
// Prepass A: guidance NCHW fp32 -> NHWC bf16 hi + lo planes (smem transpose).
// ---------------------------------------------------------------------------
__global__ __launch_bounds__(256) void transpose_split_kernel(const float* __restrict__ gin) {
    __shared__ float s[64][65];
    int blk = blockIdx.x;                  // Bq*HW/64 = 4800
    int b = blk / (HW/64);
    int pixbase = (blk - b*(HW/64)) * 64;

    for (int idx = threadIdx.x; idx < 64*64; idx += 256) {
        int c = idx >> 6, px = idx & 63;
        s[c][px] = gin[((size_t)(b*CH_G + c))*HW + pixbase + px];
    }
    __syncthreads();

    for (int idx = threadIdx.x; idx < 512; idx += 256) {
        int px = idx >> 3, q = idx & 7;
        unsigned int uh[4], ul[4];
#pragma unroll
        for (int r = 0; r < 4; r++) {
            float v0 = s[q*8 + 2*r][px];
            float v1 = s[q*8 + 2*r + 1][px];
            __nv_bfloat16 h0 = __float2bfloat16(v0);
            __nv_bfloat16 h1 = __float2bfloat16(v1);
            __nv_bfloat16 l0 = __float2bfloat16(v0 - __bfloat162float(h0));
            __nv_bfloat16 l1 = __float2bfloat16(v1 - __bfloat162float(h1));
            uh[r] = (unsigned int)__bfloat16_as_ushort(h0) | ((unsigned int)__bfloat16_as_ushort(h1) << 16);
            ul[r] = (unsigned int)__bfloat16_as_ushort(l0) | ((unsigned int)__bfloat16_as_ushort(l1) << 16);
        }
        size_t o = ((size_t)(b*HW + pixbase + px))*CH_G + q*8;
        *(uint4*)(g_hi + o) = make_uint4(uh[0], uh[1], uh[2], uh[3]);
        *(uint4*)(g_lo + o) = make_uint4(ul[0], ul[1], ul[2], ul[3]);
    }
}

// ---------------------------------------------------------------------------
// Prepass B: weights (24,64,3,3) fp32 -> padded bf16 hi/lo image.
// Row n (24 rows), col k = tap*64 + c, row stride AROW bytes.
// ---------------------------------------------------------------------------
__global__ void bprep_kernel(const float* __restrict__ wgt) {
    for (int idx = threadIdx.x; idx < COUT*576; idx += 256) {
        int n = idx / 576, k = idx - n*576;
        int c = k & 63, tap = k >> 6;
        float v = wgt[((size_t)(n*CH_G + c))*9 + tap];
        __nv_bfloat16 h = __float2bfloat16(v);
        __nv_bfloat16 l = __float2bfloat16(v - __bfloat162float(h));
        uint32_t pos = (uint32_t)n*AROW + (uint32_t)k*2;
        *(__nv_bfloat16*)(g_Bimg + pos)          = h;
        *(__nv_bfloat16*)(g_Bimg + B_HALF + pos) = l;
    }
}

// ---------------------------------------------------------------------------
// A-tile build: im2col for a 4x32 pixel tile into padded row-major smem.
// Row m = pixel p, cols k = tap*64 + c: one contiguous 128B chunk per
// (p,tap) from NHWC source. Zero-fill outside the image.
// ---------------------------------------------------------------------------
__device__ __forceinline__ void build_A(char* smem, const __nv_bfloat16* __restrict__ src,
                                        int b, int y0, int x0) {
    const uint4 z = make_uint4(0, 0, 0, 0);
    for (int t = threadIdx.x; t < 1152; t += 128) {
        int tap = t >> 7;                    // tap-major for coalesced source reads
        int p   = t & 127;
        int dy  = tap / 3 - 1;
        int dx  = tap - (tap / 3) * 3 - 1;
        int y = y0 + (p >> 5) + dy;
        int x = x0 + (p & 31) + dx;
        uint32_t base = (uint32_t)p*AROW + (uint32_t)tap*128;
        bool valid = (x >= 0) & (x < Ww) & (y >= 0) & (y < Hh);
        const uint4* sp = valid
            ? (const uint4*)(src + ((size_t)(b*HW) + (size_t)y*Ww + x)*CH_G) : (const uint4*)0;
#pragma unroll
        for (int q = 0; q < 8; q++)
            *(uint4*)(smem + base + q*16) = valid ? sp[q] : z;
    }
}

// ---------------------------------------------------------------------------
// Stage 2: conv via mma.sync.m16n8k16 bf16 (base-ISA tensor core path).
// Per CTA: D[128,24] = A[128,576] * B[24,576]^T, fp32 accum in registers;
// 3 hi/lo combos. Warp w owns m rows [32w, 32w+32) (2 m-tiles), all 3 n-tiles.
// ---------------------------------------------------------------------------
__global__ __launch_bounds__(128) void conv_mma_kernel(const float* __restrict__ bias) {
    extern __shared__ char smem[];
    int tid = threadIdx.x, wid = tid >> 5, lid = tid & 31;
    int b = blockIdx.z, y0 = blockIdx.y * 4, x0 = blockIdx.x * 32;

    // copy padded B image (both halves)
    {
        const uint4* srcb = (const uint4*)g_Bimg;
        uint4* dstb = (uint4*)(smem + SMEM_B);
        for (int i = tid; i < (2*B_HALF)/16; i += 128) dstb[i] = srcb[i];
    }
    build_A(smem, g_hi, b, y0, x0);
    __syncthreads();

    uint32_t sb = smem_u32(smem);
    // A ldmatrix lane address: m = lid%16 (+mt*16 +wid*32), k half = (lid/16)*8 elems
    uint32_t aaddr = sb + (uint32_t)(wid*32 + (lid & 15))*AROW + (uint32_t)(lid >> 4)*16;
    // B ldmatrix lane address (x2, lanes 0-15): n = lid%8, k half = ((lid/8)&1)*8 elems
    uint32_t baddr = sb + SMEM_B + (uint32_t)(lid & 7)*AROW + (uint32_t)((lid >> 3) & 1)*16;

    float acc[2][3][4];
#pragma unroll
    for (int mt = 0; mt < 2; mt++)
#pragma unroll
        for (int nt = 0; nt < 3; nt++)
#pragma unroll
            for (int r = 0; r < 4; r++) acc[mt][nt][r] = 0.f;

    // phase 1+2: A_hi * B_hi, A_hi * B_lo
#pragma unroll 1
    for (int hb = 0; hb < 2; hb++) {
        uint32_t bofs = hb * B_HALF;
#pragma unroll 2
        for (int ks = 0; ks < 36; ks++) {
            uint32_t a[2][4];
            LDSM_X4(a[0], aaddr + ks*32);
            LDSM_X4(a[1], aaddr + ks*32 + 16*AROW);
#pragma unroll
            for (int nt = 0; nt < 3; nt++) {
                uint32_t br[2];
                LDSM_X2(br, baddr + bofs + nt*8*AROW + ks*32);
                MMA_BF16(acc[0][nt], a[0], br);
                MMA_BF16(acc[1][nt], a[1], br);
            }
        }
    }

    __syncthreads();
    build_A(smem, g_lo, b, y0, x0);
    __syncthreads();

    // phase 3: A_lo * B_hi
#pragma unroll 2
    for (int ks = 0; ks < 36; ks++) {
        uint32_t a[2][4];
        LDSM_X4(a[0], aaddr + ks*32);
        LDSM_X4(a[1], aaddr + ks*32 + 16*AROW);
#pragma unroll
        for (int nt = 0; nt < 3; nt++) {
            uint32_t br[2];
            LDSM_X2(br, baddr + nt*8*AROW + ks*32);
            MMA_BF16(acc[0][nt], a[0], br);
            MMA_BF16(acc[1][nt], a[1], br);
        }
    }

    // epilogue: fragment d[mt][nt]: rows m = wid*32 + mt*16 + lid/4 (+8),
    // cols = nt*8 + (lid%4)*2 (+1). Pixel p = m: y = y0+p/32, x = x0+p%32.
#pragma unroll
    for (int mt = 0; mt < 2; mt++) {
#pragma unroll
        for (int half = 0; half < 2; half++) {
            int m = wid*32 + mt*16 + (lid >> 2) + half*8;
            int y = y0 + (m >> 5), x = x0 + (m & 31);
            float* dst = &g_oaT[(((size_t)b*HW) + (size_t)y*Ww + x)*COUT];
#pragma unroll
            for (int nt = 0; nt < 3; nt++) {
                int col = nt*8 + (lid & 3)*2;
                float2 v;
                v.x = acc[mt][nt][2*half + 0] + bias[col];
                v.y = acc[mt][nt][2*half + 1] + bias[col + 1];
                *(float2*)(dst + col) = v;
            }
        }
    }
}

// ---------------------------------------------------------------------------
// Stage 1: 2x bilinear upsample (unchanged R6).
// ---------------------------------------------------------------------------
__global__ void upsample_kernel(const float* __restrict__ fea) {
    int t = blockIdx.x * 256 + threadIdx.x;
    if (t >= Bq * HW) return;
    int b = t / HW; int pix = t - b * HW;
    int i = pix / Ww; int j = pix - i * Ww;

    int ky = i >> 1;
    int y1 = (i & 1) ? min(ky + 1, HIN - 1) : max(ky - 1, 0);
    int kx = j >> 1;
    int x1 = (j & 1) ? min(kx + 1, WIN - 1) : max(kx - 1, 0);
    const float wm = 0.75f, ws = 0.25f;

    float* dst = &g_feaT[(size_t)t * C_FEA];
#pragma unroll
    for (int c = 0; c < C_FEA; c++) {
        const float* fp = fea + ((size_t)(b * C_FEA + c)) * (HIN * WIN);
        float v00 = fp[ky * WIN + kx];
        float v01 = fp[ky * WIN + x1];
        float v10 = fp[y1 * WIN + kx];
        float v11 = fp[y1 * WIN + x1];
        dst[c] = wm * (wm * v00 + ws * v01) + ws * (wm * v10 + ws * v11);
    }
}

// ---------------------------------------------------------------------------
// Stage 3: deformable sampling (unchanged R6).
// ---------------------------------------------------------------------------
__global__ void sample_kernel() {
    int t = blockIdx.x * 256 + threadIdx.x;
    if (t >= Bq * Pn) return;
    int b = t / Pn; int p = t - b * Pn;
    int pix = p >> 3; int n = p & 7;
    int i = pix / Ww; int j = pix - i * Ww;

    float2 of = *(const float2*)(g_oaT + ((size_t)b * HW + pix) * COUT + 2 * n);
    float base = (n < 4) ? (float)i : (float)j;
    float x = of.x + base;
    float y = of.y + base;

    float x0 = floorf(x), y0 = floorf(y);
    float fx = x - x0, fy = y - y0;

    float acc0 = 0, acc1 = 0, acc2 = 0, acc3 = 0, acc4 = 0, acc5 = 0, acc6 = 0, acc7 = 0;
    const float* fb = g_feaT + (size_t)b * HW * C_FEA;
#pragma unroll
    for (int cy = 0; cy < 2; cy++) {
#pragma unroll
        for (int cx = 0; cx < 2; cx++) {
            float xi = x0 + cx, yi = y0 + cy;
            float wgt = (cy ? fy : 1.f - fy) * (cx ? fx : 1.f - fx);
            if (xi >= 0.f && xi <= (float)(Ww - 1) && yi >= 0.f && yi <= (float)(Hh - 1)) {
                int xc = (int)xi, yc = (int)yi;
                const float4* v = (const float4*)(fb + ((size_t)yc * Ww + xc) * C_FEA);
                float4 v0 = v[0], v1 = v[1];
                acc0 += wgt * v0.x; acc1 += wgt * v0.y; acc2 += wgt * v0.z; acc3 += wgt * v0.w;
                acc4 += wgt * v1.x; acc5 += wgt * v1.y; acc6 += wgt * v1.z; acc7 += wgt * v1.w;
            }
        }
    }
    float* sb = g_smp + (size_t)b * C_FEA * Pn;
    sb[(size_t)0 * Pn + p] = acc0;
    sb[(size_t)1 * Pn + p] = acc1;
    sb[(size_t)2 * Pn + p] = acc2;
    sb[(size_t)3 * Pn + p] = acc3;
    sb[(size_t)4 * Pn + p] = acc4;
    sb[(size_t)5 * Pn + p] = acc5;
    sb[(size_t)6 * Pn + p] = acc6;
    sb[(size_t)7 * Pn + p] = acc7;
}

// single-channel bilinear with zero padding (reference _bilinear_zeros)
__device__ __forceinline__ float bil1(const float* __restrict__ img, float x, float y) {
    float x0 = floorf(x), y0 = floorf(y);
    float fx = x - x0, fy = y - y0;
    float r = 0.f;
#pragma unroll
    for (int cy = 0; cy < 2; cy++) {
#pragma unroll
        for (int cx = 0; cx < 2; cx++) {
            float xi = x0 + cx, yi = y0 + cy;
            if (xi >= 0.f && xi <= (float)(Ww - 1) && yi >= 0.f && yi <= (float)(Hh - 1)) {
                float wgt = (cy ? fy : 1.f - fy) * (cx ? fx : 1.f - fx);
                r += wgt * img[(int)yi * Ww + (int)xi];
            }
        }
    }
    return r;
}

// ---------------------------------------------------------------------------
// Stage 4: fused epilogue (unchanged R6).
// ---------------------------------------------------------------------------
__global__ void final_kernel(const float* __restrict__ gt,
                             const float* __restrict__ ascp,
                             float* __restrict__ out) {
    int t = blockIdx.x * 256 + threadIdx.x;
    if (t >= Bq * HW) return;
    int b = t / HW; int pix = t - b * HW;
    int i = pix / Ww; int j = pix - i * Ww;

    float o[COUT];
    {
        const float4* ov = (const float4*)&g_oaT[(size_t)t * COUT];
#pragma unroll
        for (int h = 0; h < 6; h++) {
            float4 v = ov[h];
            o[4 * h + 0] = v.x; o[4 * h + 1] = v.y;
            o[4 * h + 2] = v.z; o[4 * h + 3] = v.w;
        }
    }

    const float4* fv = (const float4*)&g_feaT[(size_t)t * C_FEA];
    float4 f0 = fv[0], f1 = fv[1];
    float fea[8] = {f0.x, f0.y, f0.z, f0.w, f1.x, f1.y, f1.z, f1.w};

    float cw0 = 0, cw1 = 0, cw2 = 0, cw3 = 0, cw4 = 0, cw5 = 0, cw6 = 0, cw7 = 0;
#pragma unroll
    for (int a = 0; a < 8; a++) {
        int Q  = pix * 8 + a;
        int ch = Q / HW;
        int p2 = Q - ch * HW;
        const float4* sp = (const float4*)&g_smp[((size_t)(b * C_FEA + ch)) * Pn + (size_t)p2 * 8];
        float4 s0 = sp[0], s1 = sp[1];
        float fa = fea[a];
        cw0 += fa * s0.x; cw1 += fa * s0.y; cw2 += fa * s0.z; cw3 += fa * s0.w;
        cw4 += fa * s1.x; cw5 += fa * s1.y; cw6 += fa * s1.z; cw7 += fa * s1.w;
    }
    float cosw[8] = {cw0, cw1, cw2, cw3, cw4, cw5, cw6, cw7};

    float denom = ascp[0] + 1e-8f;
    const float* gb = gt + (size_t)b * HW;

    float aff[8];
#pragma unroll
    for (int n = 0; n < 8; n++) {
        float a0 = tanhf(o[16 + n] * cosw[n]) / denom;
        float y = o[2 * n]     + (float)i;   // channel 0 = dy
        float x = o[2 * n + 1] + (float)j;   // channel 1 = dx
        aff[n] = a0 * bil1(gb, x, y);
    }

    float sabs = 0.f;
#pragma unroll
    for (int n = 0; n < 8; n++) sabs += fabsf(aff[n]);
    sabs += 1e-4f;
    sabs = fmaxf(sabs, 1.0f);

    float ssum = 0.f;
#pragma unroll
    for (int n = 0; n < 8; n++) { aff[n] = aff[n] / sabs; ssum += aff[n]; }

    float v[9];
    v[0] = aff[0]; v[1] = aff[1]; v[2] = aff[2]; v[3] = aff[3];
    v[4] = 1.0f - ssum;
    v[5] = aff[4]; v[6] = aff[5]; v[7] = aff[6]; v[8] = aff[7];

    float m = v[0];
#pragma unroll
    for (int k = 1; k < 9; k++) m = fmaxf(m, v[k]);
    float e[9], es = 0.f;
#pragma unroll
    for (int k = 0; k < 9; k++) { e[k] = expf(v[k] - m); es += e[k]; }
    float inv = 1.0f / es;

    const size_t OFFA = (size_t)Bq * 18 * HW;
#pragma unroll
    for (int k = 0; k < 8; k++)
        out[((size_t)(b * 18 + k)) * HW + pix] = o[k];
    out[((size_t)(b * 18 + 8)) * HW + pix] = 0.f;
    out[((size_t)(b * 18 + 9)) * HW + pix] = 0.f;
#pragma unroll
    for (int k = 10; k < 18; k++)
        out[((size_t)(b * 18 + k)) * HW + pix] = o[k - 2];
#pragma unroll
    for (int k = 0; k < 9; k++)
        out[OFFA + ((size_t)(b * 9 + k)) * HW + pix] = e[k] * inv;
}

// ---------------------------------------------------------------------------
extern "C" void kernel_launch(void* const* d_in, const int* in_sizes, int n_in,
                              void* d_out, int out_size) {
    const float* guidance = (const float*)d_in[0];
    const float* gt       = (const float*)d_in[1];
    const float* fea      = (const float*)d_in[2];
    const float* conv_w   = (const float*)d_in[3];
    const float* conv_b   = (const float*)d_in[4];
    const float* asc      = (const float*)d_in[5];
    float* out = (float*)d_out;

    cudaFuncSetAttribute(conv_mma_kernel,
                         cudaFuncAttributeMaxDynamicSharedMemorySize, SMEM_TOTAL);

    transpose_split_kernel<<<Bq * HW / 64, 256>>>(guidance);
    bprep_kernel<<<1, 256>>>(conv_w);
    upsample_kernel<<<(Bq * HW + 255) / 256, 256>>>(fea);

    dim3 cg(Ww / 32, Hh / 4, Bq);   // 10 x 60 x 4 = 2400 CTAs, 128 threads
    conv_mma_kernel<<<cg, 128, SMEM_TOTAL>>>(conv_b);

    sample_kernel<<<(Bq * Pn + 255) / 256, 256>>>();
    final_kernel<<<(Bq * HW + 255) / 256, 256>>>(gt, asc, out);
}

// round 14
// speedup vs baseline: 1.7712x; 1.7712x over previous
#include <cuda_runtime.h>
#include <cuda_bf16.h>
#include <math.h>
#include <stdint.h>

// Problem constants
#define Bq    4
#define CH_G  64
#define Hh    240
#define Ww    320
#define HW    (Hh*Ww)          // 76800
#define NUM   8
#define C_FEA 8
#define COUT  24
#define HIN   120
#define WIN   160
#define Pn    (HW*NUM)         // 614400

// Scratch (device globals; no runtime allocation allowed)
__device__ __align__(16) float g_oaT[(size_t)Bq*HW*COUT];          // conv output, pixel-major (29.5 MB)
__device__ __align__(16) float g_feaT[(size_t)Bq*HW*C_FEA];        // upsampled fea, channel-last (9.8 MB)
__device__ __align__(16) float g_smp[(size_t)Bq*C_FEA*Pn];         // sampled tensor (78.6 MB)
__device__ __align__(16) __nv_bfloat16 g_hi[(size_t)Bq*HW*CH_G];   // guidance NHWC bf16 hi (39.3 MB)
__device__ __align__(16) __nv_bfloat16 g_lo[(size_t)Bq*HW*CH_G];   // guidance NHWC bf16 lo (39.3 MB)

// B image: 24 rows x 576 k, padded rows of 1168 B (1168 % 128 = 16 -> ldmatrix
// conflict-free). hi || lo halves.
#define BROW     1168
#define B_HALF   (24*BROW)                  // 28032
__device__ __align__(16) unsigned char g_Bimg[2*B_HALF];

// conv smem: A double buffer (per-tap slabs) + full B (hi+lo).
// A-tap slab: 128 pixels x 64 ch bf16 = 128 B data + 16 B pad = 144 B/row.
#define AT_ROW   144
#define AT_BYTES (128*AT_ROW)               // 18432
#define SMEMB    (2*AT_BYTES)               // 36864
#define SMEM_TOTAL (SMEMB + 2*B_HALF)       // 92928

// ---------------------------------------------------------------------------
// helpers
// ---------------------------------------------------------------------------
__device__ __forceinline__ uint32_t smem_u32(const void* p) {
    uint32_t a;
    asm("{ .reg .u64 t; cvta.to.shared.u64 t, %1; cvt.u32.u64 %0, t; }" : "=r"(a) : "l"(p));
    return a;
}

#define LDSM_X4(r, addr) \
    asm volatile("ldmatrix.sync.aligned.m8n8.x4.shared.b16 {%0,%1,%2,%3}, [%4];" \
        : "=r"((r)[0]), "=r"((r)[1]), "=r"((r)[2]), "=r"((r)[3]) : "r"(addr))

#define LDSM_X2(r, addr) \
    asm volatile("ldmatrix.sync.aligned.m8n8.x2.shared.b16 {%0,%1}, [%2];" \
        : "=r"((r)[0]), "=r"((r)[1]) : "r"(addr))

#define MMA_BF16(c, a, b) \
    asm volatile("mma.sync.aligned.m16n8k16.row.col.f32.bf16.bf16.f32 " \
        "{%0,%1,%2,%3}, {%4,%5,%6,%7}, {%8,%9}, {%0,%1,%2,%3};" \
        : "+f"((c)[0]), "+f"((c)[1]), "+f"((c)[2]), "+f"((c)[3]) \
        : "r"((a)[0]), "r"((a)[1]), "r"((a)[2]), "r"((a)[3]), "r"((b)[0]), "r"((b)[1]))

// ---------------------------------------------------------------------------
// Prepass A: guidance NCHW fp32 -> NHWC bf16 hi + lo planes (smem transpose).
// ---------------------------------------------------------------------------
__global__ __launch_bounds__(256) void transpose_split_kernel(const float* __restrict__ gin) {
    __shared__ float s[64][65];
    int blk = blockIdx.x;                  // Bq*HW/64 = 4800
    int b = blk / (HW/64);
    int pixbase = (blk - b*(HW/64)) * 64;

    for (int idx = threadIdx.x; idx < 64*64; idx += 256) {
        int c = idx >> 6, px = idx & 63;
        s[c][px] = gin[((size_t)(b*CH_G + c))*HW + pixbase + px];
    }
    __syncthreads();

    for (int idx = threadIdx.x; idx < 512; idx += 256) {
        int px = idx >> 3, q = idx & 7;
        unsigned int uh[4], ul[4];
#pragma unroll
        for (int r = 0; r < 4; r++) {
            float v0 = s[q*8 + 2*r][px];
            float v1 = s[q*8 + 2*r + 1][px];
            __nv_bfloat16 h0 = __float2bfloat16(v0);
            __nv_bfloat16 h1 = __float2bfloat16(v1);
            __nv_bfloat16 l0 = __float2bfloat16(v0 - __bfloat162float(h0));
            __nv_bfloat16 l1 = __float2bfloat16(v1 - __bfloat162float(h1));
            uh[r] = (unsigned int)__bfloat16_as_ushort(h0) | ((unsigned int)__bfloat16_as_ushort(h1) << 16);
            ul[r] = (unsigned int)__bfloat16_as_ushort(l0) | ((unsigned int)__bfloat16_as_ushort(l1) << 16);
        }
        size_t o = ((size_t)(b*HW + pixbase + px))*CH_G + q*8;
        *(uint4*)(g_hi + o) = make_uint4(uh[0], uh[1], uh[2], uh[3]);
        *(uint4*)(g_lo + o) = make_uint4(ul[0], ul[1], ul[2], ul[3]);
    }
}

// ---------------------------------------------------------------------------
// Prepass B: weights (24,64,3,3) fp32 -> padded bf16 hi/lo image.
// Row n (24 rows), col k = tap*64 + c, row stride BROW bytes.
// ---------------------------------------------------------------------------
__global__ void bprep_kernel(const float* __restrict__ wgt) {
    for (int idx = threadIdx.x; idx < COUT*576; idx += 256) {
        int n = idx / 576, k = idx - n*576;
        int c = k & 63, tap = k >> 6;
        float v = wgt[((size_t)(n*CH_G + c))*9 + tap];
        __nv_bfloat16 h = __float2bfloat16(v);
        __nv_bfloat16 l = __float2bfloat16(v - __bfloat162float(h));
        uint32_t pos = (uint32_t)n*BROW + (uint32_t)k*2;
        *(__nv_bfloat16*)(g_Bimg + pos)          = h;
        *(__nv_bfloat16*)(g_Bimg + B_HALF + pos) = l;
    }
}

// ---------------------------------------------------------------------------
// Per-tap A slab build via cp.async: 128 pixels x 128 B, zero-fill outside.
// 1024 x 16B ops, 4 per thread. Rows padded to 144 B (conflict-free ldsm).
// ---------------------------------------------------------------------------
__device__ __forceinline__ void issue_build(uint32_t sbase, const __nv_bfloat16* __restrict__ src,
                                            int b, int y0, int x0, int tap) {
    int dy = tap / 3 - 1;
    int dx = tap - (tap / 3) * 3 - 1;
#pragma unroll
    for (int it = 0; it < 4; it++) {
        int idx = threadIdx.x + it * 256;
        int p = idx >> 3, q = idx & 7;
        int y = y0 + (p >> 5) + dy;
        int x = x0 + (p & 31) + dx;
        bool valid = (x >= 0) & (x < Ww) & (y >= 0) & (y < Hh);
        const char* sp = valid
            ? (const char*)(src + ((size_t)b*HW + (size_t)y*Ww + x)*CH_G) + q*16
            : (const char*)src;
        uint32_t dst = sbase + (uint32_t)p*AT_ROW + (uint32_t)q*16;
        uint32_t sz = valid ? 16u : 0u;
        asm volatile("cp.async.ca.shared.global [%0], [%1], 16, %2;"
                     :: "r"(dst), "l"(sp), "r"(sz));
    }
}

// ---------------------------------------------------------------------------
// Stage 2: conv via mma.sync.m16n8k16 bf16, tap-streamed double-buffered A.
// Per CTA (256 thr, 8 warps): D[128,24] = A[128,576]*B[24,576]^T, fp32 accum;
// phase 0: A_hi x (B_hi + B_lo), phase 1: A_lo x B_hi. Warp w owns m rows
// [16w,16w+16), all 3 n-tiles. smem 90.75 KB -> 2 CTAs/SM.
// ---------------------------------------------------------------------------
__global__ __launch_bounds__(256) void conv_mma_kernel(const float* __restrict__ bias) {
    extern __shared__ char smem[];
    int tid = threadIdx.x, wid = tid >> 5, lid = tid & 31;
    int b = blockIdx.z, y0 = blockIdx.y * 4, x0 = blockIdx.x * 32;
    uint32_t sb = smem_u32(smem);

    // copy padded B image (hi + lo, 56 KB; L2-broadcast across CTAs)
    {
        const uint4* srcb = (const uint4*)g_Bimg;
        uint4* dstb = (uint4*)(smem + SMEMB);
        for (int i = tid; i < (2*B_HALF)/16; i += 256) dstb[i] = srcb[i];
    }

    float acc[3][4];
#pragma unroll
    for (int nt = 0; nt < 3; nt++)
#pragma unroll
        for (int r = 0; r < 4; r++) acc[nt][r] = 0.f;

    // lane-invariant fragment addresses
    uint32_t arow = sb + (uint32_t)(wid*16 + (lid & 15))*AT_ROW + (uint32_t)(lid >> 4)*16;
    uint32_t bbase = sb + SMEMB + (uint32_t)(lid & 7)*BROW + (uint32_t)((lid >> 3) & 1)*16;

#pragma unroll 1
    for (int ph = 0; ph < 2; ph++) {
        const __nv_bfloat16* src = ph ? g_lo : g_hi;
        int nhalves = ph ? 1 : 2;

        issue_build(sb, src, b, y0, x0, 0);
        asm volatile("cp.async.commit_group;" ::: "memory");

#pragma unroll 1
        for (int tap = 0; tap < 9; tap++) {
            if (tap < 8) {
                issue_build(sb + ((tap + 1) & 1)*AT_BYTES, src, b, y0, x0, tap + 1);
                asm volatile("cp.async.commit_group;" ::: "memory");
                asm volatile("cp.async.wait_group 1;" ::: "memory");
            } else {
                asm volatile("cp.async.wait_group 0;" ::: "memory");
            }
            __syncthreads();

            uint32_t aaddr = arow + (uint32_t)(tap & 1)*AT_BYTES;
            uint32_t btap = bbase + (uint32_t)tap*128;
#pragma unroll
            for (int ks = 0; ks < 4; ks++) {
                uint32_t a[4];
                LDSM_X4(a, aaddr + ks*32);
                for (int hb = 0; hb < nhalves; hb++) {
                    uint32_t bofs = btap + (uint32_t)hb*B_HALF + (uint32_t)ks*32;
#pragma unroll
                    for (int nt = 0; nt < 3; nt++) {
                        uint32_t br[2];
                        LDSM_X2(br, bofs + (uint32_t)nt*8*BROW);
                        MMA_BF16(acc[nt], a, br);
                    }
                }
            }
            __syncthreads();
        }
    }

    // epilogue: fragment rows m = wid*16 + lid/4 (+8), cols = nt*8 + (lid%4)*2
#pragma unroll
    for (int half = 0; half < 2; half++) {
        int m = wid*16 + (lid >> 2) + half*8;
        int y = y0 + (m >> 5), x = x0 + (m & 31);
        float* dst = &g_oaT[(((size_t)b*HW) + (size_t)y*Ww + x)*COUT];
#pragma unroll
        for (int nt = 0; nt < 3; nt++) {
            int col = nt*8 + (lid & 3)*2;
            float2 v;
            v.x = acc[nt][2*half + 0] + bias[col];
            v.y = acc[nt][2*half + 1] + bias[col + 1];
            *(float2*)(dst + col) = v;
        }
    }
}

// ---------------------------------------------------------------------------
// Stage 1: 2x bilinear upsample (unchanged R6).
// ---------------------------------------------------------------------------
__global__ void upsample_kernel(const float* __restrict__ fea) {
    int t = blockIdx.x * 256 + threadIdx.x;
    if (t >= Bq * HW) return;
    int b = t / HW; int pix = t - b * HW;
    int i = pix / Ww; int j = pix - i * Ww;

    int ky = i >> 1;
    int y1 = (i & 1) ? min(ky + 1, HIN - 1) : max(ky - 1, 0);
    int kx = j >> 1;
    int x1 = (j & 1) ? min(kx + 1, WIN - 1) : max(kx - 1, 0);
    const float wm = 0.75f, ws = 0.25f;

    float* dst = &g_feaT[(size_t)t * C_FEA];
#pragma unroll
    for (int c = 0; c < C_FEA; c++) {
        const float* fp = fea + ((size_t)(b * C_FEA + c)) * (HIN * WIN);
        float v00 = fp[ky * WIN + kx];
        float v01 = fp[ky * WIN + x1];
        float v10 = fp[y1 * WIN + kx];
        float v11 = fp[y1 * WIN + x1];
        dst[c] = wm * (wm * v00 + ws * v01) + ws * (wm * v10 + ws * v11);
    }
}

// ---------------------------------------------------------------------------
// Stage 3: deformable sampling (unchanged R6).
// ---------------------------------------------------------------------------
__global__ void sample_kernel() {
    int t = blockIdx.x * 256 + threadIdx.x;
    if (t >= Bq * Pn) return;
    int b = t / Pn; int p = t - b * Pn;
    int pix = p >> 3; int n = p & 7;
    int i = pix / Ww; int j = pix - i * Ww;

    float2 of = *(const float2*)(g_oaT + ((size_t)b * HW + pix) * COUT + 2 * n);
    float base = (n < 4) ? (float)i : (float)j;
    float x = of.x + base;
    float y = of.y + base;

    float x0 = floorf(x), y0 = floorf(y);
    float fx = x - x0, fy = y - y0;

    float acc0 = 0, acc1 = 0, acc2 = 0, acc3 = 0, acc4 = 0, acc5 = 0, acc6 = 0, acc7 = 0;
    const float* fb = g_feaT + (size_t)b * HW * C_FEA;
#pragma unroll
    for (int cy = 0; cy < 2; cy++) {
#pragma unroll
        for (int cx = 0; cx < 2; cx++) {
            float xi = x0 + cx, yi = y0 + cy;
            float wgt = (cy ? fy : 1.f - fy) * (cx ? fx : 1.f - fx);
            if (xi >= 0.f && xi <= (float)(Ww - 1) && yi >= 0.f && yi <= (float)(Hh - 1)) {
                int xc = (int)xi, yc = (int)yi;
                const float4* v = (const float4*)(fb + ((size_t)yc * Ww + xc) * C_FEA);
                float4 v0 = v[0], v1 = v[1];
                acc0 += wgt * v0.x; acc1 += wgt * v0.y; acc2 += wgt * v0.z; acc3 += wgt * v0.w;
                acc4 += wgt * v1.x; acc5 += wgt * v1.y; acc6 += wgt * v1.z; acc7 += wgt * v1.w;
            }
        }
    }
    float* sb = g_smp + (size_t)b * C_FEA * Pn;
    sb[(size_t)0 * Pn + p] = acc0;
    sb[(size_t)1 * Pn + p] = acc1;
    sb[(size_t)2 * Pn + p] = acc2;
    sb[(size_t)3 * Pn + p] = acc3;
    sb[(size_t)4 * Pn + p] = acc4;
    sb[(size_t)5 * Pn + p] = acc5;
    sb[(size_t)6 * Pn + p] = acc6;
    sb[(size_t)7 * Pn + p] = acc7;
}

// single-channel bilinear with zero padding (reference _bilinear_zeros)
__device__ __forceinline__ float bil1(const float* __restrict__ img, float x, float y) {
    float x0 = floorf(x), y0 = floorf(y);
    float fx = x - x0, fy = y - y0;
    float r = 0.f;
#pragma unroll
    for (int cy = 0; cy < 2; cy++) {
#pragma unroll
        for (int cx = 0; cx < 2; cx++) {
            float xi = x0 + cx, yi = y0 + cy;
            if (xi >= 0.f && xi <= (float)(Ww - 1) && yi >= 0.f && yi <= (float)(Hh - 1)) {
                float wgt = (cy ? fy : 1.f - fy) * (cx ? fx : 1.f - fx);
                r += wgt * img[(int)yi * Ww + (int)xi];
            }
        }
    }
    return r;
}

// ---------------------------------------------------------------------------
// Stage 4: fused epilogue (unchanged R6).
// ---------------------------------------------------------------------------
__global__ void final_kernel(const float* __restrict__ gt,
                             const float* __restrict__ ascp,
                             float* __restrict__ out) {
    int t = blockIdx.x * 256 + threadIdx.x;
    if (t >= Bq * HW) return;
    int b = t / HW; int pix = t - b * HW;
    int i = pix / Ww; int j = pix - i * Ww;

    float o[COUT];
    {
        const float4* ov = (const float4*)&g_oaT[(size_t)t * COUT];
#pragma unroll
        for (int h = 0; h < 6; h++) {
            float4 v = ov[h];
            o[4 * h + 0] = v.x; o[4 * h + 1] = v.y;
            o[4 * h + 2] = v.z; o[4 * h + 3] = v.w;
        }
    }

    const float4* fv = (const float4*)&g_feaT[(size_t)t * C_FEA];
    float4 f0 = fv[0], f1 = fv[1];
    float fea[8] = {f0.x, f0.y, f0.z, f0.w, f1.x, f1.y, f1.z, f1.w};

    float cw0 = 0, cw1 = 0, cw2 = 0, cw3 = 0, cw4 = 0, cw5 = 0, cw6 = 0, cw7 = 0;
#pragma unroll
    for (int a = 0; a < 8; a++) {
        int Q  = pix * 8 + a;
        int ch = Q / HW;
        int p2 = Q - ch * HW;
        const float4* sp = (const float4*)&g_smp[((size_t)(b * C_FEA + ch)) * Pn + (size_t)p2 * 8];
        float4 s0 = sp[0], s1 = sp[1];
        float fa = fea[a];
        cw0 += fa * s0.x; cw1 += fa * s0.y; cw2 += fa * s0.z; cw3 += fa * s0.w;
        cw4 += fa * s1.x; cw5 += fa * s1.y; cw6 += fa * s1.z; cw7 += fa * s1.w;
    }
    float cosw[8] = {cw0, cw1, cw2, cw3, cw4, cw5, cw6, cw7};

    float denom = ascp[0] + 1e-8f;
    const float* gb = gt + (size_t)b * HW;

    float aff[8];
#pragma unroll
    for (int n = 0; n < 8; n++) {
        float a0 = tanhf(o[16 + n] * cosw[n]) / denom;
        float y = o[2 * n]     + (float)i;   // channel 0 = dy
        float x = o[2 * n + 1] + (float)j;   // channel 1 = dx
        aff[n] = a0 * bil1(gb, x, y);
    }

    float sabs = 0.f;
#pragma unroll
    for (int n = 0; n < 8; n++) sabs += fabsf(aff[n]);
    sabs += 1e-4f;
    sabs = fmaxf(sabs, 1.0f);

    float ssum = 0.f;
#pragma unroll
    for (int n = 0; n < 8; n++) { aff[n] = aff[n] / sabs; ssum += aff[n]; }

    float v[9];
    v[0] = aff[0]; v[1] = aff[1]; v[2] = aff[2]; v[3] = aff[3];
    v[4] = 1.0f - ssum;
    v[5] = aff[4]; v[6] = aff[5]; v[7] = aff[6]; v[8] = aff[7];

    float m = v[0];
#pragma unroll
    for (int k = 1; k < 9; k++) m = fmaxf(m, v[k]);
    float e[9], es = 0.f;
#pragma unroll
    for (int k = 0; k < 9; k++) { e[k] = expf(v[k] - m); es += e[k]; }
    float inv = 1.0f / es;

    const size_t OFFA = (size_t)Bq * 18 * HW;
#pragma unroll
    for (int k = 0; k < 8; k++)
        out[((size_t)(b * 18 + k)) * HW + pix] = o[k];
    out[((size_t)(b * 18 + 8)) * HW + pix] = 0.f;
    out[((size_t)(b * 18 + 9)) * HW + pix] = 0.f;
#pragma unroll
    for (int k = 10; k < 18; k++)
        out[((size_t)(b * 18 + k)) * HW + pix] = o[k - 2];
#pragma unroll
    for (int k = 0; k < 9; k++)
        out[OFFA + ((size_t)(b * 9 + k)) * HW + pix] = e[k] * inv;
}

// ---------------------------------------------------------------------------
extern "C" void kernel_launch(void* const* d_in, const int* in_sizes, int n_in,
                              void* d_out, int out_size) {
    const float* guidance = (const float*)d_in[0];
    const float* gt       = (const float*)d_in[1];
    const float* fea      = (const float*)d_in[2];
    const float* conv_w   = (const float*)d_in[3];
    const float* conv_b   = (const float*)d_in[4];
    const float* asc      = (const float*)d_in[5];
    float* out = (float*)d_out;

    cudaFuncSetAttribute(conv_mma_kernel,
                         cudaFuncAttributeMaxDynamicSharedMemorySize, SMEM_TOTAL);

    transpose_split_kernel<<<Bq * HW / 64, 256>>>(guidance);
    bprep_kernel<<<1, 256>>>(conv_w);
    upsample_kernel<<<(Bq * HW + 255) / 256, 256>>>(fea);

    dim3 cg(Ww / 32, Hh / 4, Bq);   // 10 x 60 x 4 = 2400 CTAs, 256 threads
    conv_mma_kernel<<<cg, 256, SMEM_TOTAL>>>(conv_b);

    sample_kernel<<<(Bq * Pn + 255) / 256, 256>>>();
    final_kernel<<<(Bq * HW + 255) / 256, 256>>>(gt, asc, out);
}

// round 15
// speedup vs baseline: 2.0104x; 1.1350x over previous
#include <cuda_runtime.h>
#include <cuda_bf16.h>
#include <math.h>
#include <stdint.h>

// Problem constants
#define Bq    4
#define CH_G  64
#define Hh    240
#define Ww    320
#define HW    (Hh*Ww)          // 76800
#define NUM   8
#define C_FEA 8
#define COUT  24
#define HIN   120
#define WIN   160
#define Pn    (HW*NUM)         // 614400

// Scratch (device globals; no runtime allocation allowed)
__device__ __align__(16) float g_oaT[(size_t)Bq*HW*COUT];          // conv output, pixel-major (29.5 MB)
__device__ __align__(16) float g_feaT[(size_t)Bq*HW*C_FEA];        // upsampled fea, channel-last (9.8 MB)
__device__ __align__(16) float g_smp[(size_t)Bq*C_FEA*Pn];         // sampled tensor (78.6 MB)
__device__ __align__(16) __nv_bfloat16 g_hi[(size_t)Bq*HW*CH_G];   // guidance NHWC bf16 hi (39.3 MB)
__device__ __align__(16) __nv_bfloat16 g_lo[(size_t)Bq*HW*CH_G];   // guidance NHWC bf16 lo (39.3 MB)

// B image: 24 rows x 576 k, padded rows of 1168 B (1168 % 128 = 16 -> ldmatrix
// conflict-free). hi || lo halves.
#define BROW     1168
#define B_HALF   (24*BROW)                  // 28032
__device__ __align__(16) unsigned char g_Bimg[2*B_HALF];

// conv smem: guidance band (6 x 34 pixels, halo included) + full B (hi+lo).
// Band pixel chunk: 64 ch bf16 = 128 B data + 16 B pad = 144 B (conflict-free
// ldmatrix: lane stride 144 % 128 = 16).
#define PCH      144
#define BAND_CH  (6*34)                     // 204 pixel chunks
#define BAND_BYTES (BAND_CH*PCH)            // 29376
#define SMEMB    BAND_BYTES
#define SMEM_TOTAL (SMEMB + 2*B_HALF)       // 85440 -> 2 CTAs/SM

// ---------------------------------------------------------------------------
// helpers
// ---------------------------------------------------------------------------
__device__ __forceinline__ uint32_t smem_u32(const void* p) {
    uint32_t a;
    asm("{ .reg .u64 t; cvta.to.shared.u64 t, %1; cvt.u32.u64 %0, t; }" : "=r"(a) : "l"(p));
    return a;
}

#define LDSM_X4(r, addr) \
    asm volatile("ldmatrix.sync.aligned.m8n8.x4.shared.b16 {%0,%1,%2,%3}, [%4];" \
        : "=r"((r)[0]), "=r"((r)[1]), "=r"((r)[2]), "=r"((r)[3]) : "r"(addr))

#define MMA_BF16(c, a0, a1, b0, b1) \
    asm volatile("mma.sync.aligned.m16n8k16.row.col.f32.bf16.bf16.f32 " \
        "{%0,%1,%2,%3}, {%4,%5,%6,%7}, {%8,%9}, {%0,%1,%2,%3};" \
        : "+f"((c)[0]), "+f"((c)[1]), "+f"((c)[2]), "+f"((c)[3]) \
        : "r"((a0)[0]), "r"((a0)[1]), "r"((a0)[2]), "r"((a0)[3]), "r"(b0), "r"(b1))

// ---------------------------------------------------------------------------
// Prepass A: guidance NCHW fp32 -> NHWC bf16 hi + lo planes (smem transpose).
// ---------------------------------------------------------------------------
__global__ __launch_bounds__(256) void transpose_split_kernel(const float* __restrict__ gin) {
    __shared__ float s[64][65];
    int blk = blockIdx.x;                  // Bq*HW/64 = 4800
    int b = blk / (HW/64);
    int pixbase = (blk - b*(HW/64)) * 64;

    for (int idx = threadIdx.x; idx < 64*64; idx += 256) {
        int c = idx >> 6, px = idx & 63;
        s[c][px] = gin[((size_t)(b*CH_G + c))*HW + pixbase + px];
    }
    __syncthreads();

    for (int idx = threadIdx.x; idx < 512; idx += 256) {
        int px = idx >> 3, q = idx & 7;
        unsigned int uh[4], ul[4];
#pragma unroll
        for (int r = 0; r < 4; r++) {
            float v0 = s[q*8 + 2*r][px];
            float v1 = s[q*8 + 2*r + 1][px];
            __nv_bfloat16 h0 = __float2bfloat16(v0);
            __nv_bfloat16 h1 = __float2bfloat16(v1);
            __nv_bfloat16 l0 = __float2bfloat16(v0 - __bfloat162float(h0));
            __nv_bfloat16 l1 = __float2bfloat16(v1 - __bfloat162float(h1));
            uh[r] = (unsigned int)__bfloat16_as_ushort(h0) | ((unsigned int)__bfloat16_as_ushort(h1) << 16);
            ul[r] = (unsigned int)__bfloat16_as_ushort(l0) | ((unsigned int)__bfloat16_as_ushort(l1) << 16);
        }
        size_t o = ((size_t)(b*HW + pixbase + px))*CH_G + q*8;
        *(uint4*)(g_hi + o) = make_uint4(uh[0], uh[1], uh[2], uh[3]);
        *(uint4*)(g_lo + o) = make_uint4(ul[0], ul[1], ul[2], ul[3]);
    }
}

// ---------------------------------------------------------------------------
// Prepass B: weights (24,64,3,3) fp32 -> padded bf16 hi/lo image.
// ---------------------------------------------------------------------------
__global__ void bprep_kernel(const float* __restrict__ wgt) {
    for (int idx = threadIdx.x; idx < COUT*576; idx += 256) {
        int n = idx / 576, k = idx - n*576;
        int c = k & 63, tap = k >> 6;
        float v = wgt[((size_t)(n*CH_G + c))*9 + tap];
        __nv_bfloat16 h = __float2bfloat16(v);
        __nv_bfloat16 l = __float2bfloat16(v - __bfloat162float(h));
        uint32_t pos = (uint32_t)n*BROW + (uint32_t)k*2;
        *(__nv_bfloat16*)(g_Bimg + pos)          = h;
        *(__nv_bfloat16*)(g_Bimg + B_HALF + pos) = l;
    }
}

// ---------------------------------------------------------------------------
// Band load: 6x34 pixel chunks (tile + 1-px halo) x 128 B via cp.async,
// zero-filled outside the image. 1632 16B ops per call.
// ---------------------------------------------------------------------------
__device__ __forceinline__ void load_band(uint32_t sb, const __nv_bfloat16* __restrict__ src,
                                          int b, int y0, int x0) {
    for (int idx = threadIdx.x; idx < BAND_CH*8; idx += 256) {
        int chunk = idx >> 3, q = idx & 7;
        int brow = chunk / 34;
        int bcol = chunk - brow*34;
        int y = y0 + brow - 1, x = x0 + bcol - 1;
        bool valid = (x >= 0) & (x < Ww) & (y >= 0) & (y < Hh);
        const char* sp = valid
            ? (const char*)(src + ((size_t)b*HW + (size_t)y*Ww + x)*CH_G) + q*16
            : (const char*)src;
        uint32_t dst = sb + (uint32_t)chunk*PCH + (uint32_t)q*16;
        asm volatile("cp.async.ca.shared.global [%0], [%1], 16, %2;"
                     :: "r"(dst), "l"(sp), "r"(valid ? 16u : 0u));
    }
    asm volatile("cp.async.commit_group;" ::: "memory");
}

// ---------------------------------------------------------------------------
// Stage 2: conv via mma.sync.m16n8k16 bf16, banded A (no im2col!).
// Per CTA (256 thr, 8 warps): D[128,24] = A[128,576]*B[24,576]^T.
// Warp w owns pixels y = y0 + w/2, x = x0 + (w%2)*16 .. +15 (one m16 tile).
// A fragments ldmatrix'd straight out of the band with per-tap address
// offsets. B fragments via ldmatrix.x4 (2 ks-steps per instruction).
// Phase 0: A_hi x (B_hi,B_lo); phase 1: A_lo x B_hi. fp32 accum.
// ---------------------------------------------------------------------------
__global__ __launch_bounds__(256) void conv_mma_kernel(const float* __restrict__ bias) {
    extern __shared__ char smem[];
    int tid = threadIdx.x, wid = tid >> 5, lid = tid & 31;
    int b = blockIdx.z, y0 = blockIdx.y * 4, x0 = blockIdx.x * 32;
    uint32_t sb = smem_u32(smem);

    // copy padded B image (hi + lo, 56 KB; L2-resident across CTAs)
    {
        const uint4* srcb = (const uint4*)g_Bimg;
        uint4* dstb = (uint4*)(smem + SMEMB);
        for (int i = tid; i < (2*B_HALF)/16; i += 256) dstb[i] = srcb[i];
    }

    float acc[3][4];
#pragma unroll
    for (int nt = 0; nt < 3; nt++)
#pragma unroll
        for (int r = 0; r < 4; r++) acc[nt][r] = 0.f;

    // A lane base: pixel (yw, xc) at band[(yw+1)][xc+1]; k-half lid>>4.
    int yw = wid >> 1;
    int xc = (wid & 1)*16 + (lid & 15);
    uint32_t abase = sb + (uint32_t)((yw + 1)*34 + xc + 1)*PCH + (uint32_t)(lid >> 4)*16;
    // B lane base: n-row lid&7, k-matrix lid>>3 (x4 -> 4 k-offsets of 16 B).
    uint32_t bbase = sb + SMEMB + (uint32_t)(lid & 7)*BROW + (uint32_t)(lid >> 3)*16;

#pragma unroll 1
    for (int ph = 0; ph < 2; ph++) {
        load_band(sb, ph ? g_lo : g_hi, b, y0, x0);
        asm volatile("cp.async.wait_group 0;" ::: "memory");
        __syncthreads();
        int nhalves = ph ? 1 : 2;

#pragma unroll 1
        for (int tap = 0; tap < 9; tap++) {
            int dy = tap / 3 - 1;
            int dx = tap - (tap / 3)*3 - 1;
            uint32_t atap = abase + (uint32_t)((dy*34 + dx)*PCH);
            uint32_t btap = bbase + (uint32_t)tap*128;
#pragma unroll
            for (int kp = 0; kp < 2; kp++) {
                uint32_t a0[4], a1[4];
                LDSM_X4(a0, atap + kp*64);        // ks = 2kp
                LDSM_X4(a1, atap + kp*64 + 32);   // ks = 2kp+1
                for (int hb = 0; hb < nhalves; hb++) {
                    uint32_t bh = btap + (uint32_t)hb*B_HALF + (uint32_t)kp*64;
#pragma unroll
                    for (int nt = 0; nt < 3; nt++) {
                        uint32_t rb[4];
                        LDSM_X4(rb, bh + (uint32_t)nt*8*BROW);
                        MMA_BF16(acc[nt], a0, a0, rb[0], rb[1]);
                        MMA_BF16(acc[nt], a1, a1, rb[2], rb[3]);
                    }
                }
            }
        }
        if (ph == 0) __syncthreads();   // band rebuilt next phase
    }

    // epilogue: fragment rows m = wid*16 + lid/4 (+8), cols = nt*8 + (lid%4)*2
#pragma unroll
    for (int half = 0; half < 2; half++) {
        int m = wid*16 + (lid >> 2) + half*8;
        int y = y0 + (m >> 5), x = x0 + (m & 31);
        float* dst = &g_oaT[(((size_t)b*HW) + (size_t)y*Ww + x)*COUT];
#pragma unroll
        for (int nt = 0; nt < 3; nt++) {
            int col = nt*8 + (lid & 3)*2;
            float2 v;
            v.x = acc[nt][2*half + 0] + bias[col];
            v.y = acc[nt][2*half + 1] + bias[col + 1];
            *(float2*)(dst + col) = v;
        }
    }
}

// ---------------------------------------------------------------------------
// Stage 1: 2x bilinear upsample (unchanged R6).
// ---------------------------------------------------------------------------
__global__ void upsample_kernel(const float* __restrict__ fea) {
    int t = blockIdx.x * 256 + threadIdx.x;
    if (t >= Bq * HW) return;
    int b = t / HW; int pix = t - b * HW;
    int i = pix / Ww; int j = pix - i * Ww;

    int ky = i >> 1;
    int y1 = (i & 1) ? min(ky + 1, HIN - 1) : max(ky - 1, 0);
    int kx = j >> 1;
    int x1 = (j & 1) ? min(kx + 1, WIN - 1) : max(kx - 1, 0);
    const float wm = 0.75f, ws = 0.25f;

    float* dst = &g_feaT[(size_t)t * C_FEA];
#pragma unroll
    for (int c = 0; c < C_FEA; c++) {
        const float* fp = fea + ((size_t)(b * C_FEA + c)) * (HIN * WIN);
        float v00 = fp[ky * WIN + kx];
        float v01 = fp[ky * WIN + x1];
        float v10 = fp[y1 * WIN + kx];
        float v11 = fp[y1 * WIN + x1];
        dst[c] = wm * (wm * v00 + ws * v01) + ws * (wm * v10 + ws * v11);
    }
}

// ---------------------------------------------------------------------------
// Stage 3: deformable sampling (unchanged R6).
// ---------------------------------------------------------------------------
__global__ void sample_kernel() {
    int t = blockIdx.x * 256 + threadIdx.x;
    if (t >= Bq * Pn) return;
    int b = t / Pn; int p = t - b * Pn;
    int pix = p >> 3; int n = p & 7;
    int i = pix / Ww; int j = pix - i * Ww;

    float2 of = *(const float2*)(g_oaT + ((size_t)b * HW + pix) * COUT + 2 * n);
    float base = (n < 4) ? (float)i : (float)j;
    float x = of.x + base;
    float y = of.y + base;

    float x0 = floorf(x), y0 = floorf(y);
    float fx = x - x0, fy = y - y0;

    float acc0 = 0, acc1 = 0, acc2 = 0, acc3 = 0, acc4 = 0, acc5 = 0, acc6 = 0, acc7 = 0;
    const float* fb = g_feaT + (size_t)b * HW * C_FEA;
#pragma unroll
    for (int cy = 0; cy < 2; cy++) {
#pragma unroll
        for (int cx = 0; cx < 2; cx++) {
            float xi = x0 + cx, yi = y0 + cy;
            float wgt = (cy ? fy : 1.f - fy) * (cx ? fx : 1.f - fx);
            if (xi >= 0.f && xi <= (float)(Ww - 1) && yi >= 0.f && yi <= (float)(Hh - 1)) {
                int xc = (int)xi, yc = (int)yi;
                const float4* v = (const float4*)(fb + ((size_t)yc * Ww + xc) * C_FEA);
                float4 v0 = v[0], v1 = v[1];
                acc0 += wgt * v0.x; acc1 += wgt * v0.y; acc2 += wgt * v0.z; acc3 += wgt * v0.w;
                acc4 += wgt * v1.x; acc5 += wgt * v1.y; acc6 += wgt * v1.z; acc7 += wgt * v1.w;
            }
        }
    }
    float* sb = g_smp + (size_t)b * C_FEA * Pn;
    sb[(size_t)0 * Pn + p] = acc0;
    sb[(size_t)1 * Pn + p] = acc1;
    sb[(size_t)2 * Pn + p] = acc2;
    sb[(size_t)3 * Pn + p] = acc3;
    sb[(size_t)4 * Pn + p] = acc4;
    sb[(size_t)5 * Pn + p] = acc5;
    sb[(size_t)6 * Pn + p] = acc6;
    sb[(size_t)7 * Pn + p] = acc7;
}

// single-channel bilinear with zero padding (reference _bilinear_zeros)
__device__ __forceinline__ float bil1(const float* __restrict__ img, float x, float y) {
    float x0 = floorf(x), y0 = floorf(y);
    float fx = x - x0, fy = y - y0;
    float r = 0.f;
#pragma unroll
    for (int cy = 0; cy < 2; cy++) {
#pragma unroll
        for (int cx = 0; cx < 2; cx++) {
            float xi = x0 + cx, yi = y0 + cy;
            if (xi >= 0.f && xi <= (float)(Ww - 1) && yi >= 0.f && yi <= (float)(Hh - 1)) {
                float wgt = (cy ? fy : 1.f - fy) * (cx ? fx : 1.f - fx);
                r += wgt * img[(int)yi * Ww + (int)xi];
            }
        }
    }
    return r;
}

// ---------------------------------------------------------------------------
// Stage 4: fused epilogue (unchanged R6).
// ---------------------------------------------------------------------------
__global__ void final_kernel(const float* __restrict__ gt,
                             const float* __restrict__ ascp,
                             float* __restrict__ out) {
    int t = blockIdx.x * 256 + threadIdx.x;
    if (t >= Bq * HW) return;
    int b = t / HW; int pix = t - b * HW;
    int i = pix / Ww; int j = pix - i * Ww;

    float o[COUT];
    {
        const float4* ov = (const float4*)&g_oaT[(size_t)t * COUT];
#pragma unroll
        for (int h = 0; h < 6; h++) {
            float4 v = ov[h];
            o[4 * h + 0] = v.x; o[4 * h + 1] = v.y;
            o[4 * h + 2] = v.z; o[4 * h + 3] = v.w;
        }
    }

    const float4* fv = (const float4*)&g_feaT[(size_t)t * C_FEA];
    float4 f0 = fv[0], f1 = fv[1];
    float fea[8] = {f0.x, f0.y, f0.z, f0.w, f1.x, f1.y, f1.z, f1.w};

    float cw0 = 0, cw1 = 0, cw2 = 0, cw3 = 0, cw4 = 0, cw5 = 0, cw6 = 0, cw7 = 0;
#pragma unroll
    for (int a = 0; a < 8; a++) {
        int Q  = pix * 8 + a;
        int ch = Q / HW;
        int p2 = Q - ch * HW;
        const float4* sp = (const float4*)&g_smp[((size_t)(b * C_FEA + ch)) * Pn + (size_t)p2 * 8];
        float4 s0 = sp[0], s1 = sp[1];
        float fa = fea[a];
        cw0 += fa * s0.x; cw1 += fa * s0.y; cw2 += fa * s0.z; cw3 += fa * s0.w;
        cw4 += fa * s1.x; cw5 += fa * s1.y; cw6 += fa * s1.z; cw7 += fa * s1.w;
    }
    float cosw[8] = {cw0, cw1, cw2, cw3, cw4, cw5, cw6, cw7};

    float denom = ascp[0] + 1e-8f;
    const float* gb = gt + (size_t)b * HW;

    float aff[8];
#pragma unroll
    for (int n = 0; n < 8; n++) {
        float a0 = tanhf(o[16 + n] * cosw[n]) / denom;
        float y = o[2 * n]     + (float)i;   // channel 0 = dy
        float x = o[2 * n + 1] + (float)j;   // channel 1 = dx
        aff[n] = a0 * bil1(gb, x, y);
    }

    float sabs = 0.f;
#pragma unroll
    for (int n = 0; n < 8; n++) sabs += fabsf(aff[n]);
    sabs += 1e-4f;
    sabs = fmaxf(sabs, 1.0f);

    float ssum = 0.f;
#pragma unroll
    for (int n = 0; n < 8; n++) { aff[n] = aff[n] / sabs; ssum += aff[n]; }

    float v[9];
    v[0] = aff[0]; v[1] = aff[1]; v[2] = aff[2]; v[3] = aff[3];
    v[4] = 1.0f - ssum;
    v[5] = aff[4]; v[6] = aff[5]; v[7] = aff[6]; v[8] = aff[7];

    float m = v[0];
#pragma unroll
    for (int k = 1; k < 9; k++) m = fmaxf(m, v[k]);
    float e[9], es = 0.f;
#pragma unroll
    for (int k = 0; k < 9; k++) { e[k] = expf(v[k] - m); es += e[k]; }
    float inv = 1.0f / es;

    const size_t OFFA = (size_t)Bq * 18 * HW;
#pragma unroll
    for (int k = 0; k < 8; k++)
        out[((size_t)(b * 18 + k)) * HW + pix] = o[k];
    out[((size_t)(b * 18 + 8)) * HW + pix] = 0.f;
    out[((size_t)(b * 18 + 9)) * HW + pix] = 0.f;
#pragma unroll
    for (int k = 10; k < 18; k++)
        out[((size_t)(b * 18 + k)) * HW + pix] = o[k - 2];
#pragma unroll
    for (int k = 0; k < 9; k++)
        out[OFFA + ((size_t)(b * 9 + k)) * HW + pix] = e[k] * inv;
}

// ---------------------------------------------------------------------------
extern "C" void kernel_launch(void* const* d_in, const int* in_sizes, int n_in,
                              void* d_out, int out_size) {
    const float* guidance = (const float*)d_in[0];
    const float* gt       = (const float*)d_in[1];
    const float* fea      = (const float*)d_in[2];
    const float* conv_w   = (const float*)d_in[3];
    const float* conv_b   = (const float*)d_in[4];
    const float* asc      = (const float*)d_in[5];
    float* out = (float*)d_out;

    cudaFuncSetAttribute(conv_mma_kernel,
                         cudaFuncAttributeMaxDynamicSharedMemorySize, SMEM_TOTAL);

    transpose_split_kernel<<<Bq * HW / 64, 256>>>(guidance);
    bprep_kernel<<<1, 256>>>(conv_w);
    upsample_kernel<<<(Bq * HW + 255) / 256, 256>>>(fea);

    dim3 cg(Ww / 32, Hh / 4, Bq);   // 10 x 60 x 4 = 2400 CTAs, 256 threads
    conv_mma_kernel<<<cg, 256, SMEM_TOTAL>>>(conv_b);

    sample_kernel<<<(Bq * Pn + 255) / 256, 256>>>();
    final_kernel<<<(Bq * HW + 255) / 256, 256>>>(gt, asc, out);
}